// round 4
// baseline (speedup 1.0000x reference)
#include <cuda_runtime.h>
#include <math.h>

#define N_NODES  50000
#define N_EDGES  800000
#define NODE_DIM 64
#define EDGE_DIM 32
#define HID      128
#define EPB      8

typedef unsigned long long ull;

// Scratch: per-node precomputed rows [ns(128) | nd(128) | cs(128) | cd(128)]
__device__ float g_A[(size_t)N_NODES * 512];
// Folded edge-path weights
__device__ float g_Mn[32 * 128];
__device__ float g_Mc[32 * 128];
__device__ float g_bn[128];
__device__ float g_bc[128];
// Rearranged Wn2: WA[i*32+l] = Wn2[4i..4i+3][2l], WB same for 2l+1
__device__ float4 g_WA[1024];
__device__ float4 g_WB[1024];

union F4 { float4 f; ulonglong2 u; };

__device__ __forceinline__ ull pk2(float x, float y) {
    ull r; asm("mov.b64 %0,{%1,%2};" : "=l"(r) : "f"(x), "f"(y)); return r;
}
__device__ __forceinline__ void upk2(ull v, float& x, float& y) {
    asm("mov.b64 {%0,%1},%2;" : "=f"(x), "=f"(y) : "l"(v));
}
__device__ __forceinline__ ull ffma2(ull a, ull b, ull c) {
    ull d; asm("fma.rn.f32x2 %0,%1,%2,%3;" : "=l"(d) : "l"(a), "l"(b), "l"(c)); return d;
}
__device__ __forceinline__ ull fadd2(ull a, ull b) {
    ull d; asm("add.rn.f32x2 %0,%1,%2;" : "=l"(d) : "l"(a), "l"(b)); return d;
}
// silu via MUFU tanh: silu(z) = hz + hz*tanh(hz), hz = z/2
__device__ __forceinline__ float silu1(float z) {
    float hz = 0.5f * z;
    float th;
    asm("tanh.approx.f32 %0, %1;" : "=f"(th) : "f"(hz));
    return fmaf(hz, th, hz);
}

// ---------------------------------------------------------------------------
// K0: fold edge-path weights + rearrange Wn2
// ---------------------------------------------------------------------------
__global__ void k_fold(const float* __restrict__ We2, const float* __restrict__ be2,
                       const float* __restrict__ Wn1, const float* __restrict__ bn1,
                       const float* __restrict__ Wc1, const float* __restrict__ bc1,
                       const float* __restrict__ Wn2) {
    int j = threadIdx.x;  // 0..127
    float bn = bn1[j], bc = bc1[j];
    for (int b = 0; b < 32; b++) {
        bn += be2[b] * Wn1[(128 + b) * 128 + j];
        bc += be2[b] * Wc1[(128 + b) * 128 + j];
    }
    g_bn[j] = bn;
    g_bc[j] = bc;
    for (int a = 0; a < 32; a++) {
        float sn = 0.f, sc = 0.f;
        for (int b = 0; b < 32; b++) {
            float w = We2[a * 32 + b];
            sn += w * Wn1[(128 + b) * 128 + j];
            sc += w * Wc1[(128 + b) * 128 + j];
        }
        g_Mn[a * 128 + j] = sn;
        g_Mc[a * 128 + j] = sc;
    }
    for (int idx = j; idx < 1024; idx += 128) {
        int i = idx >> 5, l = idx & 31;
        g_WA[idx] = make_float4(Wn2[(4 * i + 0) * 64 + 2 * l], Wn2[(4 * i + 1) * 64 + 2 * l],
                                Wn2[(4 * i + 2) * 64 + 2 * l], Wn2[(4 * i + 3) * 64 + 2 * l]);
        g_WB[idx] = make_float4(Wn2[(4 * i + 0) * 64 + 2 * l + 1], Wn2[(4 * i + 1) * 64 + 2 * l + 1],
                                Wn2[(4 * i + 2) * 64 + 2 * l + 1], Wn2[(4 * i + 3) * 64 + 2 * l + 1]);
    }
}

// ---------------------------------------------------------------------------
// K1: per-node precompute, f32x2 math. 128 threads, NPB nodes per block.
// ---------------------------------------------------------------------------
#define NPB 16
__global__ void k_node(const float* __restrict__ h,
                       const float* __restrict__ Wn1,
                       const float* __restrict__ Wc1) {
    __shared__ ull h2[NPB * 64];   // duplicated {h,h} pairs
    int node0 = blockIdx.x * NPB;
    for (int i = threadIdx.x; i < NPB * 64; i += 128) {
        float hv = h[node0 * 64 + i];
        h2[i] = pk2(hv, hv);
    }
    __syncthreads();
    int j = threadIdx.x;
    int m = j >> 5;
    int c = (j & 31) * 4;
    const float* W = ((m & 2) ? Wc1 : Wn1) + ((m & 1) ? 64 * 128 : 0);

    ull a0[NPB], a1[NPB];
#pragma unroll
    for (int n = 0; n < NPB; n++) { a0[n] = 0ull; a1[n] = 0ull; }
#pragma unroll 4
    for (int k = 0; k < 64; k++) {
        F4 w; w.f = *(const float4*)&W[k * 128 + c];
#pragma unroll
        for (int n = 0; n < NPB; n++) {
            ull hv = h2[n * 64 + k];
            a0[n] = ffma2(hv, w.u.x, a0[n]);
            a1[n] = ffma2(hv, w.u.y, a1[n]);
        }
    }
#pragma unroll
    for (int n = 0; n < NPB; n++) {
        F4 r; r.u.x = a0[n]; r.u.y = a1[n];
        *(float4*)&g_A[(size_t)(node0 + n) * 512 + m * 128 + c] = r.f;
    }
}

// ---------------------------------------------------------------------------
// K2: initialize output with (h, x)
// ---------------------------------------------------------------------------
__global__ void k_init(const float* __restrict__ h, const float* __restrict__ x,
                       float* __restrict__ out) {
    int nh = N_NODES * NODE_DIM;
    int tot = nh + N_NODES * 3;
    for (int i = blockIdx.x * blockDim.x + threadIdx.x; i < tot; i += gridDim.x * blockDim.x)
        out[i] = (i < nh) ? h[i] : x[i - nh];
}

// ---------------------------------------------------------------------------
// K3: edge kernel. EPB=8 edges/warp-iter, f32x2 math, smem t-broadcast.
// ---------------------------------------------------------------------------
__global__ void __launch_bounds__(256, 2)
k_edge(const float* __restrict__ dist,
       const int*   __restrict__ eidx,
       const float* __restrict__ x,
       const float* __restrict__ We1, const float* __restrict__ be1,
       const float* __restrict__ bn2,
       const float* __restrict__ Wc2,
       float* __restrict__ out) {
    extern __shared__ float sm[];
    float*  Mn_sh = sm;                        // 4096
    float*  Mc_sh = Mn_sh + 4096;              // 4096
    float4* WA_sh = (float4*)(Mc_sh + 4096);   // 1024 f4
    float4* WB_sh = WA_sh + 1024;              // 1024 f4
    float*  gbuf  = (float*)(WB_sh + 1024);    // 8 warps * 1024
    float*  bn_sh  = gbuf + 8192;
    float*  bc_sh  = bn_sh + 128;
    float*  Wc2_sh = bc_sh + 128;
    float*  bn2_sh = Wc2_sh + 128;
    float*  We1_sh = bn2_sh + 64;
    float*  be1_sh = We1_sh + 32;

    for (int i = threadIdx.x; i < 4096; i += blockDim.x) {
        Mn_sh[i] = g_Mn[i];
        Mc_sh[i] = g_Mc[i];
    }
    for (int i = threadIdx.x; i < 1024; i += blockDim.x) {
        WA_sh[i] = g_WA[i];
        WB_sh[i] = g_WB[i];
    }
    if (threadIdx.x < 128) {
        bn_sh[threadIdx.x]  = g_bn[threadIdx.x];
        bc_sh[threadIdx.x]  = g_bc[threadIdx.x];
        Wc2_sh[threadIdx.x] = Wc2[threadIdx.x];
    }
    if (threadIdx.x < 64) bn2_sh[threadIdx.x] = bn2[threadIdx.x];
    if (threadIdx.x < 32) {
        We1_sh[threadIdx.x] = We1[threadIdx.x];
        be1_sh[threadIdx.x] = be1[threadIdx.x];
    }
    __syncthreads();

    const int lane = threadIdx.x & 31;
    const int wib  = threadIdx.x >> 5;
    const int gw   = blockIdx.x * (blockDim.x >> 5) + wib;
    const int nw   = gridDim.x * (blockDim.x >> 5);

    const float w_e1  = We1_sh[lane];
    const float b_e1v = be1_sh[lane];
    F4 bn4;   bn4.f   = *(const float4*)&bn_sh[4 * lane];
    F4 bc4;   bc4.f   = *(const float4*)&bc_sh[4 * lane];
    F4 wc2_4; wc2_4.f = *(const float4*)&Wc2_sh[4 * lane];
    const float2 bn2_2 = *(const float2*)&bn2_sh[2 * lane];
    float* gb = gbuf + wib * 1024;
    ull*   t2w = (ull*)gb;                    // 32k x 8ee dup pairs (2KB, dies before gn)
    const float4* t2f = (const float4*)gb;
    const float4* A4  = (const float4*)g_A;
    const float4* Mn4 = (const float4*)Mn_sh;
    const float4* Mc4 = (const float4*)Mc_sh;
    const float4* gb4 = (const float4*)gb;
    float* out_x = out + (size_t)N_NODES * 64;

    for (int base = gw * EPB; base < N_EDGES; base += nw * EPB) {
        int4 sA = *(const int4*)&eidx[base];
        int4 sB = *(const int4*)&eidx[base + 4];
        int4 dA = *(const int4*)&eidx[N_EDGES + base];
        int4 dB = *(const int4*)&eidx[N_EDGES + base + 4];
        float4 qA = *(const float4*)&dist[base];
        float4 qB = *(const float4*)&dist[base + 4];
        int src[EPB]  = {sA.x, sA.y, sA.z, sA.w, sB.x, sB.y, sB.z, sB.w};
        int dstn[EPB] = {dA.x, dA.y, dA.z, dA.w, dB.x, dB.y, dB.z, dB.w};
        float dq[EPB] = {qA.x, qA.y, qA.z, qA.w, qB.x, qB.y, qB.z, qB.w};

        // t per lane (lane = k), store duplicated swizzled pairs
        {
            int s = lane & 6;
#pragma unroll
            for (int ee = 0; ee < EPB; ee++) {
                float t = silu1(dq[ee] * w_e1 + b_e1v);
                t2w[lane * 8 + (ee ^ s)] = pk2(t, t);
            }
        }
        __syncwarp();

        // ---- phase pc: coord-MLP hidden -> cw ----
        ull pcl[EPB], pch[EPB];
#pragma unroll
        for (int ee = 0; ee < EPB; ee++) {
            F4 c; c.f = A4[(size_t)src[ee]  * 128 + 64 + lane];
            F4 d; d.f = A4[(size_t)dstn[ee] * 128 + 96 + lane];
            pcl[ee] = fadd2(fadd2(c.u.x, d.u.x), bc4.u.x);
            pch[ee] = fadd2(fadd2(c.u.y, d.u.y), bc4.u.y);
        }
#pragma unroll
        for (int k = 0; k < 32; k++) {
            F4 mc; mc.f = Mc4[k * 32 + lane];
            int sh = (k >> 1) & 3;
#pragma unroll
            for (int eep = 0; eep < 4; eep++) {
                F4 tt; tt.f = t2f[k * 4 + (eep ^ sh)];
                pcl[2 * eep]     = ffma2(tt.u.x, mc.u.x, pcl[2 * eep]);
                pch[2 * eep]     = ffma2(tt.u.x, mc.u.y, pch[2 * eep]);
                pcl[2 * eep + 1] = ffma2(tt.u.y, mc.u.x, pcl[2 * eep + 1]);
                pch[2 * eep + 1] = ffma2(tt.u.y, mc.u.y, pch[2 * eep + 1]);
            }
        }
        float cw[EPB];
#pragma unroll
        for (int ee = 0; ee < EPB; ee++) {
            float p0, p1, p2, p3;
            upk2(pcl[ee], p0, p1);
            upk2(pch[ee], p2, p3);
            float s = silu1(p0) * wc2_4.f.x + silu1(p1) * wc2_4.f.y
                    + silu1(p2) * wc2_4.f.z + silu1(p3) * wc2_4.f.w;
#pragma unroll
            for (int off = 16; off > 0; off >>= 1)
                s += __shfl_xor_sync(0xffffffffu, s, off);
            cw[ee] = s;
        }

        // ---- coord scatter (lanes 0..7) ----
        if (lane < EPB) {
            float mycw = cw[0]; int ms = src[0], md = dstn[0];
#pragma unroll
            for (int ee = 1; ee < EPB; ee++)
                if (lane == ee) { mycw = cw[ee]; ms = src[ee]; md = dstn[ee]; }
            float dx = x[ms * 3 + 0] - x[md * 3 + 0];
            float dy = x[ms * 3 + 1] - x[md * 3 + 1];
            float dz = x[ms * 3 + 2] - x[md * 3 + 2];
            float len = fmaxf(sqrtf(dx * dx + dy * dy + dz * dz), 1e-8f);
            float inv = mycw / len;
            float* ox = out_x + (size_t)md * 3;
            atomicAdd(&ox[0], dx * inv);
            atomicAdd(&ox[1], dy * inv);
            atomicAdd(&ox[2], dz * inv);
        }

        // ---- phase pn: node-MLP hidden ----
        ull pnl[EPB], pnh[EPB];
#pragma unroll
        for (int ee = 0; ee < EPB; ee++) {
            F4 a; a.f = A4[(size_t)src[ee]  * 128 + lane];
            F4 b; b.f = A4[(size_t)dstn[ee] * 128 + 32 + lane];
            pnl[ee] = fadd2(fadd2(a.u.x, b.u.x), bn4.u.x);
            pnh[ee] = fadd2(fadd2(a.u.y, b.u.y), bn4.u.y);
        }
#pragma unroll
        for (int k = 0; k < 32; k++) {
            F4 mn; mn.f = Mn4[k * 32 + lane];
            int sh = (k >> 1) & 3;
#pragma unroll
            for (int eep = 0; eep < 4; eep++) {
                F4 tt; tt.f = t2f[k * 4 + (eep ^ sh)];
                pnl[2 * eep]     = ffma2(tt.u.x, mn.u.x, pnl[2 * eep]);
                pnh[2 * eep]     = ffma2(tt.u.x, mn.u.y, pnh[2 * eep]);
                pnl[2 * eep + 1] = ffma2(tt.u.y, mn.u.x, pnl[2 * eep + 1]);
                pnh[2 * eep + 1] = ffma2(tt.u.y, mn.u.y, pnh[2 * eep + 1]);
            }
        }
        __syncwarp();   // all lanes done reading t2 before gn overwrites it

#pragma unroll
        for (int ee = 0; ee < EPB; ee++) {
            float p0, p1, p2, p3;
            upk2(pnl[ee], p0, p1);
            upk2(pnh[ee], p2, p3);
            float4 gn = make_float4(silu1(p0), silu1(p1), silu1(p2), silu1(p3));
            *(float4*)&gb[ee * 128 + 4 * lane] = gn;
        }
        __syncwarp();

        // ---- phase 2: gn(128) @ Wn2 -> 64 ----
        ull macA[EPB], macB[EPB];
#pragma unroll
        for (int ee = 0; ee < EPB; ee++) {
            macA[ee] = pk2(bn2_2.x, 0.f);
            macB[ee] = pk2(bn2_2.y, 0.f);
        }
#pragma unroll
        for (int i = 0; i < 32; i++) {
            F4 wA; wA.f = WA_sh[i * 32 + lane];
            F4 wB; wB.f = WB_sh[i * 32 + lane];
#pragma unroll
            for (int ee = 0; ee < EPB; ee++) {
                F4 g; g.f = gb4[ee * 32 + i];  // broadcast
                macA[ee] = ffma2(g.u.x, wA.u.x, macA[ee]);
                macA[ee] = ffma2(g.u.y, wA.u.y, macA[ee]);
                macB[ee] = ffma2(g.u.x, wB.u.x, macB[ee]);
                macB[ee] = ffma2(g.u.y, wB.u.y, macB[ee]);
            }
        }

        // ---- node message scatter (scalar atomics: HW REDG fast path) ----
#pragma unroll
        for (int ee = 0; ee < EPB; ee++) {
            float a0, a1, b0, b1;
            upk2(macA[ee], a0, a1);
            upk2(macB[ee], b0, b1);
            float* oh = out + (size_t)dstn[ee] * 64;
            atomicAdd(&oh[2 * lane],     a0 + a1);
            atomicAdd(&oh[2 * lane + 1], b0 + b1);
        }
    }
}

// ---------------------------------------------------------------------------
extern "C" void kernel_launch(void* const* d_in, const int* in_sizes, int n_in,
                              void* d_out, int out_size) {
    const float* h    = (const float*)d_in[0];
    const float* x    = (const float*)d_in[1];
    const float* dist = (const float*)d_in[2];
    const float* We1  = (const float*)d_in[3];
    const float* be1  = (const float*)d_in[4];
    const float* We2  = (const float*)d_in[5];
    const float* be2  = (const float*)d_in[6];
    const float* Wn1  = (const float*)d_in[7];
    const float* bn1  = (const float*)d_in[8];
    const float* Wn2  = (const float*)d_in[9];
    const float* bn2  = (const float*)d_in[10];
    const float* Wc1  = (const float*)d_in[11];
    const float* bc1  = (const float*)d_in[12];
    const float* Wc2  = (const float*)d_in[13];
    const int*   eidx = (const int*)d_in[14];
    float* out = (float*)d_out;

    static bool attr_set = false;
    if (!attr_set) {
        cudaFuncSetAttribute(k_edge, cudaFuncAttributeMaxDynamicSharedMemorySize, 101 * 1024);
        attr_set = true;
    }

    k_fold<<<1, 128>>>(We2, be2, Wn1, bn1, Wc1, bc1, Wn2);
    k_node<<<N_NODES / NPB, 128>>>(h, Wn1, Wc1);
    k_init<<<2048, 256>>>(h, x, out);

    const int smem = 25088 * sizeof(float);  // 100352 B
    k_edge<<<296, 256, smem>>>(dist, eidx, x, We1, be1, bn2, Wc2, out);
}

// round 5
// speedup vs baseline: 1.0428x; 1.0428x over previous
#include <cuda_runtime.h>
#include <math.h>

#define N_NODES  50000
#define N_EDGES  800000
#define NODE_DIM 64
#define EDGE_DIM 32
#define HID      128
#define EPB      8

typedef unsigned long long ull;

// Scratch: per-node precomputed rows [ns(128) | nd(128) | cs(128) | cd(128)]
__device__ float g_A[(size_t)N_NODES * 512];
// Folded edge-path weights
__device__ float g_Mn[32 * 128];
__device__ float g_Mc[32 * 128];
__device__ float g_bn[128];
__device__ float g_bc[128];
// Rearranged Wn2: WA[i*32+l] = Wn2[4i..4i+3][2l], WB same for 2l+1
__device__ float4 g_WA[1024];
__device__ float4 g_WB[1024];

union F4 { float4 f; ulonglong2 u; };

__device__ __forceinline__ ull pk2(float x, float y) {
    ull r; asm("mov.b64 %0,{%1,%2};" : "=l"(r) : "f"(x), "f"(y)); return r;
}
__device__ __forceinline__ void upk2(ull v, float& x, float& y) {
    asm("mov.b64 {%0,%1},%2;" : "=f"(x), "=f"(y) : "l"(v));
}
__device__ __forceinline__ ull ffma2(ull a, ull b, ull c) {
    ull d; asm("fma.rn.f32x2 %0,%1,%2,%3;" : "=l"(d) : "l"(a), "l"(b), "l"(c)); return d;
}
__device__ __forceinline__ ull fadd2(ull a, ull b) {
    ull d; asm("add.rn.f32x2 %0,%1,%2;" : "=l"(d) : "l"(a), "l"(b)); return d;
}
// silu via MUFU tanh: silu(z) = hz + hz*tanh(hz), hz = z/2
__device__ __forceinline__ float silu1(float z) {
    float hz = 0.5f * z;
    float th;
    asm("tanh.approx.f32 %0, %1;" : "=f"(th) : "f"(hz));
    return fmaf(hz, th, hz);
}

// ---------------------------------------------------------------------------
// K0: fold edge-path weights + rearrange Wn2
// ---------------------------------------------------------------------------
__global__ void k_fold(const float* __restrict__ We2, const float* __restrict__ be2,
                       const float* __restrict__ Wn1, const float* __restrict__ bn1,
                       const float* __restrict__ Wc1, const float* __restrict__ bc1,
                       const float* __restrict__ Wn2) {
    int j = threadIdx.x;  // 0..127
    float bn = bn1[j], bc = bc1[j];
    for (int b = 0; b < 32; b++) {
        bn += be2[b] * Wn1[(128 + b) * 128 + j];
        bc += be2[b] * Wc1[(128 + b) * 128 + j];
    }
    g_bn[j] = bn;
    g_bc[j] = bc;
    for (int a = 0; a < 32; a++) {
        float sn = 0.f, sc = 0.f;
        for (int b = 0; b < 32; b++) {
            float w = We2[a * 32 + b];
            sn += w * Wn1[(128 + b) * 128 + j];
            sc += w * Wc1[(128 + b) * 128 + j];
        }
        g_Mn[a * 128 + j] = sn;
        g_Mc[a * 128 + j] = sc;
    }
    for (int idx = j; idx < 1024; idx += 128) {
        int i = idx >> 5, l = idx & 31;
        g_WA[idx] = make_float4(Wn2[(4 * i + 0) * 64 + 2 * l], Wn2[(4 * i + 1) * 64 + 2 * l],
                                Wn2[(4 * i + 2) * 64 + 2 * l], Wn2[(4 * i + 3) * 64 + 2 * l]);
        g_WB[idx] = make_float4(Wn2[(4 * i + 0) * 64 + 2 * l + 1], Wn2[(4 * i + 1) * 64 + 2 * l + 1],
                                Wn2[(4 * i + 2) * 64 + 2 * l + 1], Wn2[(4 * i + 3) * 64 + 2 * l + 1]);
    }
}

// ---------------------------------------------------------------------------
// K1: per-node precompute, f32x2 math. 128 threads, NPB nodes per block.
// ---------------------------------------------------------------------------
#define NPB 16
__global__ void k_node(const float* __restrict__ h,
                       const float* __restrict__ Wn1,
                       const float* __restrict__ Wc1) {
    __shared__ ull h2[NPB * 64];   // duplicated {h,h} pairs
    int node0 = blockIdx.x * NPB;
    for (int i = threadIdx.x; i < NPB * 64; i += 128) {
        float hv = h[node0 * 64 + i];
        h2[i] = pk2(hv, hv);
    }
    __syncthreads();
    int j = threadIdx.x;
    int m = j >> 5;
    int c = (j & 31) * 4;
    const float* W = ((m & 2) ? Wc1 : Wn1) + ((m & 1) ? 64 * 128 : 0);

    ull a0[NPB], a1[NPB];
#pragma unroll
    for (int n = 0; n < NPB; n++) { a0[n] = 0ull; a1[n] = 0ull; }
#pragma unroll 4
    for (int k = 0; k < 64; k++) {
        F4 w; w.f = *(const float4*)&W[k * 128 + c];
#pragma unroll
        for (int n = 0; n < NPB; n++) {
            ull hv = h2[n * 64 + k];
            a0[n] = ffma2(hv, w.u.x, a0[n]);
            a1[n] = ffma2(hv, w.u.y, a1[n]);
        }
    }
#pragma unroll
    for (int n = 0; n < NPB; n++) {
        F4 r; r.u.x = a0[n]; r.u.y = a1[n];
        *(float4*)&g_A[(size_t)(node0 + n) * 512 + m * 128 + c] = r.f;
    }
}

// ---------------------------------------------------------------------------
// K2: initialize output with (h, x)
// ---------------------------------------------------------------------------
__global__ void k_init(const float* __restrict__ h, const float* __restrict__ x,
                       float* __restrict__ out) {
    int nh = N_NODES * NODE_DIM;
    int tot = nh + N_NODES * 3;
    for (int i = blockIdx.x * blockDim.x + threadIdx.x; i < tot; i += gridDim.x * blockDim.x)
        out[i] = (i < nh) ? h[i] : x[i - nh];
}

// ---------------------------------------------------------------------------
// K3: edge kernel. EPB=8 edges/warp-iter, f32x2 math, smem t-broadcast.
// Structure is round-2's kernel; t broadcast moved from shfl to smem.
// ---------------------------------------------------------------------------
__global__ void __launch_bounds__(256, 2)
k_edge(const float* __restrict__ dist,
       const int*   __restrict__ eidx,
       const float* __restrict__ x,
       const float* __restrict__ We1, const float* __restrict__ be1,
       const float* __restrict__ bn2,
       const float* __restrict__ Wc2,
       float* __restrict__ out) {
    extern __shared__ float sm[];
    float*  Mn_sh = sm;                        // 4096
    float*  Mc_sh = Mn_sh + 4096;              // 4096
    float4* WA_sh = (float4*)(Mc_sh + 4096);   // 1024 f4
    float4* WB_sh = WA_sh + 1024;              // 1024 f4
    float*  gbuf  = (float*)(WB_sh + 1024);    // 8 warps * 1024
    float*  bn_sh  = gbuf + 8192;
    float*  bc_sh  = bn_sh + 128;
    float*  Wc2_sh = bc_sh + 128;
    float*  bn2_sh = Wc2_sh + 128;
    float*  We1_sh = bn2_sh + 64;
    float*  be1_sh = We1_sh + 32;

    for (int i = threadIdx.x; i < 4096; i += blockDim.x) {
        Mn_sh[i] = g_Mn[i];
        Mc_sh[i] = g_Mc[i];
    }
    for (int i = threadIdx.x; i < 1024; i += blockDim.x) {
        WA_sh[i] = g_WA[i];
        WB_sh[i] = g_WB[i];
    }
    if (threadIdx.x < 128) {
        bn_sh[threadIdx.x]  = g_bn[threadIdx.x];
        bc_sh[threadIdx.x]  = g_bc[threadIdx.x];
        Wc2_sh[threadIdx.x] = Wc2[threadIdx.x];
    }
    if (threadIdx.x < 64) bn2_sh[threadIdx.x] = bn2[threadIdx.x];
    if (threadIdx.x < 32) {
        We1_sh[threadIdx.x] = We1[threadIdx.x];
        be1_sh[threadIdx.x] = be1[threadIdx.x];
    }
    __syncthreads();

    const int lane = threadIdx.x & 31;
    const int wib  = threadIdx.x >> 5;
    const int gw   = blockIdx.x * (blockDim.x >> 5) + wib;
    const int nw   = gridDim.x * (blockDim.x >> 5);

    const float w_e1  = We1_sh[lane];
    const float b_e1v = be1_sh[lane];
    F4 bn4;   bn4.f   = *(const float4*)&bn_sh[4 * lane];
    F4 bc4;   bc4.f   = *(const float4*)&bc_sh[4 * lane];
    F4 wc2_4; wc2_4.f = *(const float4*)&Wc2_sh[4 * lane];
    const float2 bn2_2 = *(const float2*)&bn2_sh[2 * lane];
    float* gb = gbuf + wib * 1024;
    ull*   t2w = (ull*)gb;                    // t dup pairs (2KB, dies before gn store)
    const float4* t2f = (const float4*)gb;
    const float4* A4  = (const float4*)g_A;
    const float4* Mn4 = (const float4*)Mn_sh;
    const float4* Mc4 = (const float4*)Mc_sh;
    const float4* gb4 = (const float4*)gb;
    float* out_x = out + (size_t)N_NODES * 64;

    for (int base = gw * EPB; base < N_EDGES; base += nw * EPB) {
        // Scalar lazy loads (round-2 style, low register pressure).
        int src[EPB], dstn[EPB];
        {
            const int s = lane & 6;
#pragma unroll
            for (int ee = 0; ee < EPB; ee++) {
                int e = base + ee;
                float d = dist[e];
                src[ee]  = eidx[e];
                dstn[ee] = eidx[N_EDGES + e];
                float t = silu1(d * w_e1 + b_e1v);   // lane = k of edge-MLP
                t2w[lane * 8 + (ee ^ s)] = pk2(t, t);
            }
        }
        __syncwarp();

        // ---- phase pc: coord-MLP hidden -> cw ----
        ull pcl[EPB], pch[EPB];
#pragma unroll
        for (int ee = 0; ee < EPB; ee++) {
            F4 c; c.f = A4[(size_t)src[ee]  * 128 + 64 + lane];
            F4 d; d.f = A4[(size_t)dstn[ee] * 128 + 96 + lane];
            pcl[ee] = fadd2(fadd2(c.u.x, d.u.x), bc4.u.x);
            pch[ee] = fadd2(fadd2(c.u.y, d.u.y), bc4.u.y);
        }
#pragma unroll
        for (int k = 0; k < 32; k++) {
            F4 mc; mc.f = Mc4[k * 32 + lane];
            const int sh = (k >> 1) & 3;
#pragma unroll
            for (int eep = 0; eep < 4; eep++) {
                F4 tt; tt.f = t2f[k * 4 + (eep ^ sh)];
                pcl[2 * eep]     = ffma2(tt.u.x, mc.u.x, pcl[2 * eep]);
                pch[2 * eep]     = ffma2(tt.u.x, mc.u.y, pch[2 * eep]);
                pcl[2 * eep + 1] = ffma2(tt.u.y, mc.u.x, pcl[2 * eep + 1]);
                pch[2 * eep + 1] = ffma2(tt.u.y, mc.u.y, pch[2 * eep + 1]);
            }
        }
        float cw[EPB];
#pragma unroll
        for (int ee = 0; ee < EPB; ee++) {
            float p0, p1, p2, p3;
            upk2(pcl[ee], p0, p1);
            upk2(pch[ee], p2, p3);
            float s = silu1(p0) * wc2_4.f.x + silu1(p1) * wc2_4.f.y
                    + silu1(p2) * wc2_4.f.z + silu1(p3) * wc2_4.f.w;
#pragma unroll
            for (int off = 16; off > 0; off >>= 1)
                s += __shfl_xor_sync(0xffffffffu, s, off);
            cw[ee] = s;
        }

        // ---- coord scatter (lanes 0..7) ----
        if (lane < EPB) {
            float mycw = cw[0]; int ms = src[0], md = dstn[0];
#pragma unroll
            for (int ee = 1; ee < EPB; ee++)
                if (lane == ee) { mycw = cw[ee]; ms = src[ee]; md = dstn[ee]; }
            float dx = x[ms * 3 + 0] - x[md * 3 + 0];
            float dy = x[ms * 3 + 1] - x[md * 3 + 1];
            float dz = x[ms * 3 + 2] - x[md * 3 + 2];
            float len = fmaxf(sqrtf(dx * dx + dy * dy + dz * dz), 1e-8f);
            float inv = mycw / len;
            float* ox = out_x + (size_t)md * 3;
            atomicAdd(&ox[0], dx * inv);
            atomicAdd(&ox[1], dy * inv);
            atomicAdd(&ox[2], dz * inv);
        }

        // ---- phase pn: node-MLP hidden ----
        ull pnl[EPB], pnh[EPB];
#pragma unroll
        for (int ee = 0; ee < EPB; ee++) {
            F4 a; a.f = A4[(size_t)src[ee]  * 128 + lane];
            F4 b; b.f = A4[(size_t)dstn[ee] * 128 + 32 + lane];
            pnl[ee] = fadd2(fadd2(a.u.x, b.u.x), bn4.u.x);
            pnh[ee] = fadd2(fadd2(a.u.y, b.u.y), bn4.u.y);
        }
#pragma unroll
        for (int k = 0; k < 32; k++) {
            F4 mn; mn.f = Mn4[k * 32 + lane];
            const int sh = (k >> 1) & 3;
#pragma unroll
            for (int eep = 0; eep < 4; eep++) {
                F4 tt; tt.f = t2f[k * 4 + (eep ^ sh)];
                pnl[2 * eep]     = ffma2(tt.u.x, mn.u.x, pnl[2 * eep]);
                pnh[2 * eep]     = ffma2(tt.u.x, mn.u.y, pnh[2 * eep]);
                pnl[2 * eep + 1] = ffma2(tt.u.y, mn.u.x, pnl[2 * eep + 1]);
                pnh[2 * eep + 1] = ffma2(tt.u.y, mn.u.y, pnh[2 * eep + 1]);
            }
        }
        __syncwarp();   // all lanes done reading t2 before gn overwrites it

#pragma unroll
        for (int ee = 0; ee < EPB; ee++) {
            float p0, p1, p2, p3;
            upk2(pnl[ee], p0, p1);
            upk2(pnh[ee], p2, p3);
            float4 gn = make_float4(silu1(p0), silu1(p1), silu1(p2), silu1(p3));
            *(float4*)&gb[ee * 128 + 4 * lane] = gn;
        }
        __syncwarp();

        // ---- phase 2: gn(128) @ Wn2 -> 64 ----
        ull macA[EPB], macB[EPB];
#pragma unroll
        for (int ee = 0; ee < EPB; ee++) {
            macA[ee] = pk2(bn2_2.x, 0.f);
            macB[ee] = pk2(bn2_2.y, 0.f);
        }
#pragma unroll
        for (int i = 0; i < 32; i++) {
            F4 wA; wA.f = WA_sh[i * 32 + lane];
            F4 wB; wB.f = WB_sh[i * 32 + lane];
#pragma unroll
            for (int ee = 0; ee < EPB; ee++) {
                F4 g; g.f = gb4[ee * 32 + i];  // broadcast
                macA[ee] = ffma2(g.u.x, wA.u.x, macA[ee]);
                macA[ee] = ffma2(g.u.y, wA.u.y, macA[ee]);
                macB[ee] = ffma2(g.u.x, wB.u.x, macB[ee]);
                macB[ee] = ffma2(g.u.y, wB.u.y, macB[ee]);
            }
        }

        // ---- node message scatter (scalar atomics: HW REDG fast path) ----
#pragma unroll
        for (int ee = 0; ee < EPB; ee++) {
            float a0, a1, b0, b1;
            upk2(macA[ee], a0, a1);
            upk2(macB[ee], b0, b1);
            float* oh = out + (size_t)dstn[ee] * 64;
            atomicAdd(&oh[2 * lane],     a0 + a1);
            atomicAdd(&oh[2 * lane + 1], b0 + b1);
        }
    }
}

// ---------------------------------------------------------------------------
extern "C" void kernel_launch(void* const* d_in, const int* in_sizes, int n_in,
                              void* d_out, int out_size) {
    const float* h    = (const float*)d_in[0];
    const float* x    = (const float*)d_in[1];
    const float* dist = (const float*)d_in[2];
    const float* We1  = (const float*)d_in[3];
    const float* be1  = (const float*)d_in[4];
    const float* We2  = (const float*)d_in[5];
    const float* be2  = (const float*)d_in[6];
    const float* Wn1  = (const float*)d_in[7];
    const float* bn1  = (const float*)d_in[8];
    const float* Wn2  = (const float*)d_in[9];
    const float* bn2  = (const float*)d_in[10];
    const float* Wc1  = (const float*)d_in[11];
    const float* bc1  = (const float*)d_in[12];
    const float* Wc2  = (const float*)d_in[13];
    const int*   eidx = (const int*)d_in[14];
    float* out = (float*)d_out;

    static bool attr_set = false;
    if (!attr_set) {
        cudaFuncSetAttribute(k_edge, cudaFuncAttributeMaxDynamicSharedMemorySize, 101 * 1024);
        attr_set = true;
    }

    k_fold<<<1, 128>>>(We2, be2, Wn1, bn1, Wc1, bc1, Wn2);
    k_node<<<N_NODES / NPB, 128>>>(h, Wn1, Wc1);
    k_init<<<2048, 256>>>(h, x, out);

    const int smem = 25088 * sizeof(float);  // 100352 B
    k_edge<<<296, 256, smem>>>(dist, eidx, x, We1, be1, bn2, Wc2, out);
}

// round 6
// speedup vs baseline: 1.1697x; 1.1217x over previous
#include <cuda_runtime.h>
#include <math.h>

#define N_NODES  50000
#define N_EDGES  800000
#define NODE_DIM 64
#define EDGE_DIM 32
#define HID      128
#define EPB      8
#define TPB      192          // 6 warps/block, 2 blocks/SM -> 170-reg cap (no spills)
#define WPB      (TPB / 32)

typedef unsigned long long ull;

// Scratch: per-node precomputed rows [ns(128) | nd(128) | cs(128) | cd(128)]
__device__ float g_A[(size_t)N_NODES * 512];
// Folded edge-path weights
__device__ float g_Mn[32 * 128];
__device__ float g_Mc[32 * 128];
__device__ float g_bn[128];
__device__ float g_bc[128];
// Rearranged Wn2: WA[i*32+l] = Wn2[4i..4i+3][2l], WB same for 2l+1
__device__ float4 g_WA[1024];
__device__ float4 g_WB[1024];

union F4 { float4 f; ulonglong2 u; };

__device__ __forceinline__ ull pk2(float x, float y) {
    ull r; asm("mov.b64 %0,{%1,%2};" : "=l"(r) : "f"(x), "f"(y)); return r;
}
__device__ __forceinline__ void upk2(ull v, float& x, float& y) {
    asm("mov.b64 {%0,%1},%2;" : "=f"(x), "=f"(y) : "l"(v));
}
__device__ __forceinline__ ull ffma2(ull a, ull b, ull c) {
    ull d; asm("fma.rn.f32x2 %0,%1,%2,%3;" : "=l"(d) : "l"(a), "l"(b), "l"(c)); return d;
}
__device__ __forceinline__ ull fadd2(ull a, ull b) {
    ull d; asm("add.rn.f32x2 %0,%1,%2;" : "=l"(d) : "l"(a), "l"(b)); return d;
}
// silu via MUFU tanh: silu(z) = hz + hz*tanh(hz), hz = z/2
__device__ __forceinline__ float silu1(float z) {
    float hz = 0.5f * z;
    float th;
    asm("tanh.approx.f32 %0, %1;" : "=f"(th) : "f"(hz));
    return fmaf(hz, th, hz);
}

// ---------------------------------------------------------------------------
// K0: fold edge-path weights + rearrange Wn2
// ---------------------------------------------------------------------------
__global__ void k_fold(const float* __restrict__ We2, const float* __restrict__ be2,
                       const float* __restrict__ Wn1, const float* __restrict__ bn1,
                       const float* __restrict__ Wc1, const float* __restrict__ bc1,
                       const float* __restrict__ Wn2) {
    int j = threadIdx.x;  // 0..127
    float bn = bn1[j], bc = bc1[j];
    for (int b = 0; b < 32; b++) {
        bn += be2[b] * Wn1[(128 + b) * 128 + j];
        bc += be2[b] * Wc1[(128 + b) * 128 + j];
    }
    g_bn[j] = bn;
    g_bc[j] = bc;
    for (int a = 0; a < 32; a++) {
        float sn = 0.f, sc = 0.f;
        for (int b = 0; b < 32; b++) {
            float w = We2[a * 32 + b];
            sn += w * Wn1[(128 + b) * 128 + j];
            sc += w * Wc1[(128 + b) * 128 + j];
        }
        g_Mn[a * 128 + j] = sn;
        g_Mc[a * 128 + j] = sc;
    }
    for (int idx = j; idx < 1024; idx += 128) {
        int i = idx >> 5, l = idx & 31;
        g_WA[idx] = make_float4(Wn2[(4 * i + 0) * 64 + 2 * l], Wn2[(4 * i + 1) * 64 + 2 * l],
                                Wn2[(4 * i + 2) * 64 + 2 * l], Wn2[(4 * i + 3) * 64 + 2 * l]);
        g_WB[idx] = make_float4(Wn2[(4 * i + 0) * 64 + 2 * l + 1], Wn2[(4 * i + 1) * 64 + 2 * l + 1],
                                Wn2[(4 * i + 2) * 64 + 2 * l + 1], Wn2[(4 * i + 3) * 64 + 2 * l + 1]);
    }
}

// ---------------------------------------------------------------------------
// K1: per-node precompute, f32x2 math. 128 threads, NPB nodes per block.
// ---------------------------------------------------------------------------
#define NPB 16
__global__ void k_node(const float* __restrict__ h,
                       const float* __restrict__ Wn1,
                       const float* __restrict__ Wc1) {
    __shared__ ull h2[NPB * 64];   // duplicated {h,h} pairs
    int node0 = blockIdx.x * NPB;
    for (int i = threadIdx.x; i < NPB * 64; i += 128) {
        float hv = h[node0 * 64 + i];
        h2[i] = pk2(hv, hv);
    }
    __syncthreads();
    int j = threadIdx.x;
    int m = j >> 5;
    int c = (j & 31) * 4;
    const float* W = ((m & 2) ? Wc1 : Wn1) + ((m & 1) ? 64 * 128 : 0);

    ull a0[NPB], a1[NPB];
#pragma unroll
    for (int n = 0; n < NPB; n++) { a0[n] = 0ull; a1[n] = 0ull; }
#pragma unroll 4
    for (int k = 0; k < 64; k++) {
        F4 w; w.f = *(const float4*)&W[k * 128 + c];
#pragma unroll
        for (int n = 0; n < NPB; n++) {
            ull hv = h2[n * 64 + k];
            a0[n] = ffma2(hv, w.u.x, a0[n]);
            a1[n] = ffma2(hv, w.u.y, a1[n]);
        }
    }
#pragma unroll
    for (int n = 0; n < NPB; n++) {
        F4 r; r.u.x = a0[n]; r.u.y = a1[n];
        *(float4*)&g_A[(size_t)(node0 + n) * 512 + m * 128 + c] = r.f;
    }
}

// ---------------------------------------------------------------------------
// K2: initialize output with (h, x)
// ---------------------------------------------------------------------------
__global__ void k_init(const float* __restrict__ h, const float* __restrict__ x,
                       float* __restrict__ out) {
    int nh = N_NODES * NODE_DIM;
    int tot = nh + N_NODES * 3;
    for (int i = blockIdx.x * blockDim.x + threadIdx.x; i < tot; i += gridDim.x * blockDim.x)
        out[i] = (i < nh) ? h[i] : x[i - nh];
}

// ---------------------------------------------------------------------------
// K3: edge kernel. EPB=8 edges/warp-iter, f32x2 math, smem t-broadcast.
// 192 threads/block, 2 blocks/SM -> 170-register cap (spill-free).
// ---------------------------------------------------------------------------
__global__ void __launch_bounds__(TPB, 2)
k_edge(const float* __restrict__ dist,
       const int*   __restrict__ eidx,
       const float* __restrict__ x,
       const float* __restrict__ We1, const float* __restrict__ be1,
       const float* __restrict__ bn2,
       const float* __restrict__ Wc2,
       float* __restrict__ out) {
    extern __shared__ float sm[];
    float*  Mn_sh = sm;                        // 4096
    float*  Mc_sh = Mn_sh + 4096;              // 4096
    float4* WA_sh = (float4*)(Mc_sh + 4096);   // 1024 f4
    float4* WB_sh = WA_sh + 1024;              // 1024 f4
    float*  gbuf  = (float*)(WB_sh + 1024);    // WPB warps * 1024
    float*  bn_sh  = gbuf + WPB * 1024;
    float*  bc_sh  = bn_sh + 128;
    float*  Wc2_sh = bc_sh + 128;
    float*  bn2_sh = Wc2_sh + 128;
    float*  We1_sh = bn2_sh + 64;
    float*  be1_sh = We1_sh + 32;

    for (int i = threadIdx.x; i < 4096; i += blockDim.x) {
        Mn_sh[i] = g_Mn[i];
        Mc_sh[i] = g_Mc[i];
    }
    for (int i = threadIdx.x; i < 1024; i += blockDim.x) {
        WA_sh[i] = g_WA[i];
        WB_sh[i] = g_WB[i];
    }
    if (threadIdx.x < 128) {
        bn_sh[threadIdx.x]  = g_bn[threadIdx.x];
        bc_sh[threadIdx.x]  = g_bc[threadIdx.x];
        Wc2_sh[threadIdx.x] = Wc2[threadIdx.x];
    }
    if (threadIdx.x < 64) bn2_sh[threadIdx.x] = bn2[threadIdx.x];
    if (threadIdx.x < 32) {
        We1_sh[threadIdx.x] = We1[threadIdx.x];
        be1_sh[threadIdx.x] = be1[threadIdx.x];
    }
    __syncthreads();

    const int lane = threadIdx.x & 31;
    const int wib  = threadIdx.x >> 5;
    const int gw   = blockIdx.x * WPB + wib;
    const int nw   = gridDim.x * WPB;

    const float w_e1  = We1_sh[lane];
    const float b_e1v = be1_sh[lane];
    F4 bn4;   bn4.f   = *(const float4*)&bn_sh[4 * lane];
    F4 bc4;   bc4.f   = *(const float4*)&bc_sh[4 * lane];
    F4 wc2_4; wc2_4.f = *(const float4*)&Wc2_sh[4 * lane];
    const float2 bn2_2 = *(const float2*)&bn2_sh[2 * lane];
    float* gb = gbuf + wib * 1024;
    ull*   t2w = (ull*)gb;                    // t dup pairs (2KB, dies before gn store)
    const float4* t2f = (const float4*)gb;
    const float4* A4  = (const float4*)g_A;
    const float4* Mn4 = (const float4*)Mn_sh;
    const float4* Mc4 = (const float4*)Mc_sh;
    const float4* gb4 = (const float4*)gb;
    float* out_x = out + (size_t)N_NODES * 64;

    for (int base = gw * EPB; base < N_EDGES; base += nw * EPB) {
        // Scalar lazy loads, low register pressure.
        int src[EPB], dstn[EPB];
        {
            const int s = lane & 6;
#pragma unroll
            for (int ee = 0; ee < EPB; ee++) {
                int e = base + ee;
                float d = dist[e];
                src[ee]  = eidx[e];
                dstn[ee] = eidx[N_EDGES + e];
                float t = silu1(d * w_e1 + b_e1v);   // lane = k of edge-MLP
                t2w[lane * 8 + (ee ^ s)] = pk2(t, t);
            }
        }
        __syncwarp();

        // ---- phase pc: coord-MLP hidden -> cw ----
        ull pcl[EPB], pch[EPB];
#pragma unroll
        for (int ee = 0; ee < EPB; ee++) {
            F4 c; c.f = A4[(size_t)src[ee]  * 128 + 64 + lane];
            F4 d; d.f = A4[(size_t)dstn[ee] * 128 + 96 + lane];
            pcl[ee] = fadd2(fadd2(c.u.x, d.u.x), bc4.u.x);
            pch[ee] = fadd2(fadd2(c.u.y, d.u.y), bc4.u.y);
        }
#pragma unroll
        for (int k = 0; k < 32; k++) {
            F4 mc; mc.f = Mc4[k * 32 + lane];
            const int sh = (k >> 1) & 3;
#pragma unroll
            for (int eep = 0; eep < 4; eep++) {
                F4 tt; tt.f = t2f[k * 4 + (eep ^ sh)];
                pcl[2 * eep]     = ffma2(tt.u.x, mc.u.x, pcl[2 * eep]);
                pch[2 * eep]     = ffma2(tt.u.x, mc.u.y, pch[2 * eep]);
                pcl[2 * eep + 1] = ffma2(tt.u.y, mc.u.x, pcl[2 * eep + 1]);
                pch[2 * eep + 1] = ffma2(tt.u.y, mc.u.y, pch[2 * eep + 1]);
            }
        }
        float cw[EPB];
#pragma unroll
        for (int ee = 0; ee < EPB; ee++) {
            float p0, p1, p2, p3;
            upk2(pcl[ee], p0, p1);
            upk2(pch[ee], p2, p3);
            float s = silu1(p0) * wc2_4.f.x + silu1(p1) * wc2_4.f.y
                    + silu1(p2) * wc2_4.f.z + silu1(p3) * wc2_4.f.w;
#pragma unroll
            for (int off = 16; off > 0; off >>= 1)
                s += __shfl_xor_sync(0xffffffffu, s, off);
            cw[ee] = s;
        }

        // ---- coord scatter (lanes 0..7) ----
        if (lane < EPB) {
            float mycw = cw[0]; int ms = src[0], md = dstn[0];
#pragma unroll
            for (int ee = 1; ee < EPB; ee++)
                if (lane == ee) { mycw = cw[ee]; ms = src[ee]; md = dstn[ee]; }
            float dx = x[ms * 3 + 0] - x[md * 3 + 0];
            float dy = x[ms * 3 + 1] - x[md * 3 + 1];
            float dz = x[ms * 3 + 2] - x[md * 3 + 2];
            float len = fmaxf(sqrtf(dx * dx + dy * dy + dz * dz), 1e-8f);
            float inv = mycw / len;
            float* ox = out_x + (size_t)md * 3;
            atomicAdd(&ox[0], dx * inv);
            atomicAdd(&ox[1], dy * inv);
            atomicAdd(&ox[2], dz * inv);
        }

        // ---- phase pn: node-MLP hidden ----
        ull pnl[EPB], pnh[EPB];
#pragma unroll
        for (int ee = 0; ee < EPB; ee++) {
            F4 a; a.f = A4[(size_t)src[ee]  * 128 + lane];
            F4 b; b.f = A4[(size_t)dstn[ee] * 128 + 32 + lane];
            pnl[ee] = fadd2(fadd2(a.u.x, b.u.x), bn4.u.x);
            pnh[ee] = fadd2(fadd2(a.u.y, b.u.y), bn4.u.y);
        }
#pragma unroll
        for (int k = 0; k < 32; k++) {
            F4 mn; mn.f = Mn4[k * 32 + lane];
            const int sh = (k >> 1) & 3;
#pragma unroll
            for (int eep = 0; eep < 4; eep++) {
                F4 tt; tt.f = t2f[k * 4 + (eep ^ sh)];
                pnl[2 * eep]     = ffma2(tt.u.x, mn.u.x, pnl[2 * eep]);
                pnh[2 * eep]     = ffma2(tt.u.x, mn.u.y, pnh[2 * eep]);
                pnl[2 * eep + 1] = ffma2(tt.u.y, mn.u.x, pnl[2 * eep + 1]);
                pnh[2 * eep + 1] = ffma2(tt.u.y, mn.u.y, pnh[2 * eep + 1]);
            }
        }
        __syncwarp();   // all lanes done reading t2 before gn overwrites it

#pragma unroll
        for (int ee = 0; ee < EPB; ee++) {
            float p0, p1, p2, p3;
            upk2(pnl[ee], p0, p1);
            upk2(pnh[ee], p2, p3);
            float4 gn = make_float4(silu1(p0), silu1(p1), silu1(p2), silu1(p3));
            *(float4*)&gb[ee * 128 + 4 * lane] = gn;
        }
        __syncwarp();

        // ---- phase 2: gn(128) @ Wn2 -> 64 ----
        ull macA[EPB], macB[EPB];
#pragma unroll
        for (int ee = 0; ee < EPB; ee++) {
            macA[ee] = pk2(bn2_2.x, 0.f);
            macB[ee] = pk2(bn2_2.y, 0.f);
        }
#pragma unroll
        for (int i = 0; i < 32; i++) {
            F4 wA; wA.f = WA_sh[i * 32 + lane];
            F4 wB; wB.f = WB_sh[i * 32 + lane];
#pragma unroll
            for (int ee = 0; ee < EPB; ee++) {
                F4 g; g.f = gb4[ee * 32 + i];  // broadcast
                macA[ee] = ffma2(g.u.x, wA.u.x, macA[ee]);
                macA[ee] = ffma2(g.u.y, wA.u.y, macA[ee]);
                macB[ee] = ffma2(g.u.x, wB.u.x, macB[ee]);
                macB[ee] = ffma2(g.u.y, wB.u.y, macB[ee]);
            }
        }

        // ---- node message scatter (scalar atomics: HW REDG fast path) ----
#pragma unroll
        for (int ee = 0; ee < EPB; ee++) {
            float a0, a1, b0, b1;
            upk2(macA[ee], a0, a1);
            upk2(macB[ee], b0, b1);
            float* oh = out + (size_t)dstn[ee] * 64;
            atomicAdd(&oh[2 * lane],     a0 + a1);
            atomicAdd(&oh[2 * lane + 1], b0 + b1);
        }
    }
}

// ---------------------------------------------------------------------------
extern "C" void kernel_launch(void* const* d_in, const int* in_sizes, int n_in,
                              void* d_out, int out_size) {
    const float* h    = (const float*)d_in[0];
    const float* x    = (const float*)d_in[1];
    const float* dist = (const float*)d_in[2];
    const float* We1  = (const float*)d_in[3];
    const float* be1  = (const float*)d_in[4];
    const float* We2  = (const float*)d_in[5];
    const float* be2  = (const float*)d_in[6];
    const float* Wn1  = (const float*)d_in[7];
    const float* bn1  = (const float*)d_in[8];
    const float* Wn2  = (const float*)d_in[9];
    const float* bn2  = (const float*)d_in[10];
    const float* Wc1  = (const float*)d_in[11];
    const float* bc1  = (const float*)d_in[12];
    const float* Wc2  = (const float*)d_in[13];
    const int*   eidx = (const int*)d_in[14];
    float* out = (float*)d_out;

    static bool attr_set = false;
    if (!attr_set) {
        cudaFuncSetAttribute(k_edge, cudaFuncAttributeMaxDynamicSharedMemorySize, 93 * 1024);
        attr_set = true;
    }

    k_fold<<<1, 128>>>(We2, be2, Wn1, bn1, Wc1, bc1, Wn2);
    k_node<<<N_NODES / NPB, 128>>>(h, Wn1, Wc1);
    k_init<<<2048, 256>>>(h, x, out);

    // smem: 16384 (Mn,Mc,WA,WB) + WPB*1024 (gbuf) + 512 small = 23040 floats
    const int smem = (16384 + WPB * 1024 + 512) * sizeof(float);  // 92160 B
    k_edge<<<296, TPB, smem>>>(dist, eidx, x, We1, be1, bn2, Wc2, out);
}

// round 7
// speedup vs baseline: 9.2127x; 7.8758x over previous
#include <cuda_runtime.h>
#include <math.h>

#define N_NODES  50000
#define N_EDGES  800000
#define NODE_DIM 64
#define EDGE_DIM 32
#define HID      128
#define EPB      8
#define TPB      256
#define WPB      (TPB / 32)
#define NB       4096          // table bins over d in [0,15]

typedef unsigned long long ull;

// Per-node precomputed rows [ns(128) | nd(128) | cs(128) | cd(128)]
__device__ float g_A[(size_t)N_NODES * 512];
// Folded edge-path weights (used only to build the table)
__device__ float g_Mn[32 * 128];
__device__ float g_Mc[32 * 128];
__device__ float g_bn[128];
__device__ float g_bc[128];
// Interp table: row i = [F(d_i)+bn (128) | G(d_i)+bc (128)], d_i = i*15/NB
__device__ float g_T[(size_t)(NB + 1) * 256];
// Rearranged Wn2: WA[i*32+l] = Wn2[4i..4i+3][2l], WB same for 2l+1
__device__ float4 g_WA[1024];
__device__ float4 g_WB[1024];

union F4 { float4 f; ulonglong2 u; };

__device__ __forceinline__ ull pk2(float x, float y) {
    ull r; asm("mov.b64 %0,{%1,%2};" : "=l"(r) : "f"(x), "f"(y)); return r;
}
__device__ __forceinline__ void upk2(ull v, float& x, float& y) {
    asm("mov.b64 {%0,%1},%2;" : "=f"(x), "=f"(y) : "l"(v));
}
__device__ __forceinline__ ull ffma2(ull a, ull b, ull c) {
    ull d; asm("fma.rn.f32x2 %0,%1,%2,%3;" : "=l"(d) : "l"(a), "l"(b), "l"(c)); return d;
}
__device__ __forceinline__ ull fadd2(ull a, ull b) {
    ull d; asm("add.rn.f32x2 %0,%1,%2;" : "=l"(d) : "l"(a), "l"(b)); return d;
}
// silu via MUFU tanh: silu(z) = hz + hz*tanh(hz), hz = z/2
__device__ __forceinline__ float silu1(float z) {
    float hz = 0.5f * z;
    float th;
    asm("tanh.approx.f32 %0, %1;" : "=f"(th) : "f"(hz));
    return fmaf(hz, th, hz);
}

// ---------------------------------------------------------------------------
// K0: fold edge-path weights + rearrange Wn2
// ---------------------------------------------------------------------------
__global__ void k_fold(const float* __restrict__ We2, const float* __restrict__ be2,
                       const float* __restrict__ Wn1, const float* __restrict__ bn1,
                       const float* __restrict__ Wc1, const float* __restrict__ bc1,
                       const float* __restrict__ Wn2) {
    int j = threadIdx.x;  // 0..127
    float bn = bn1[j], bc = bc1[j];
    for (int b = 0; b < 32; b++) {
        bn += be2[b] * Wn1[(128 + b) * 128 + j];
        bc += be2[b] * Wc1[(128 + b) * 128 + j];
    }
    g_bn[j] = bn;
    g_bc[j] = bc;
    for (int a = 0; a < 32; a++) {
        float sn = 0.f, sc = 0.f;
        for (int b = 0; b < 32; b++) {
            float w = We2[a * 32 + b];
            sn += w * Wn1[(128 + b) * 128 + j];
            sc += w * Wc1[(128 + b) * 128 + j];
        }
        g_Mn[a * 128 + j] = sn;
        g_Mc[a * 128 + j] = sc;
    }
    for (int idx = j; idx < 1024; idx += 128) {
        int i = idx >> 5, l = idx & 31;
        g_WA[idx] = make_float4(Wn2[(4 * i + 0) * 64 + 2 * l], Wn2[(4 * i + 1) * 64 + 2 * l],
                                Wn2[(4 * i + 2) * 64 + 2 * l], Wn2[(4 * i + 3) * 64 + 2 * l]);
        g_WB[idx] = make_float4(Wn2[(4 * i + 0) * 64 + 2 * l + 1], Wn2[(4 * i + 1) * 64 + 2 * l + 1],
                                Wn2[(4 * i + 2) * 64 + 2 * l + 1], Wn2[(4 * i + 3) * 64 + 2 * l + 1]);
    }
}

// ---------------------------------------------------------------------------
// K0b: build edge-path interp table. One block per bin, 256 threads.
// ---------------------------------------------------------------------------
__global__ void k_tab(const float* __restrict__ We1, const float* __restrict__ be1) {
    __shared__ float t_sh[32];
    int i = blockIdx.x;           // 0..NB
    int j = threadIdx.x;          // 0..255
    float d = (15.0f / NB) * i;
    if (j < 32) {
        float z = d * We1[j] + be1[j];
        // exact silu for the table (cheap here, better accuracy)
        t_sh[j] = z / (1.f + __expf(-z));
    }
    __syncthreads();
    const float* M = (j < 128) ? g_Mn : g_Mc;
    const float* bb = (j < 128) ? g_bn : g_bc;
    int jj = j & 127;
    float s = bb[jj];
#pragma unroll 8
    for (int k = 0; k < 32; k++) s += t_sh[k] * M[k * 128 + jj];
    g_T[(size_t)i * 256 + j] = s;
}

// ---------------------------------------------------------------------------
// K1: per-node precompute, f32x2 math. 128 threads, NPB nodes per block.
// ---------------------------------------------------------------------------
#define NPB 16
__global__ void k_node(const float* __restrict__ h,
                       const float* __restrict__ Wn1,
                       const float* __restrict__ Wc1) {
    __shared__ ull h2[NPB * 64];   // duplicated {h,h} pairs
    int node0 = blockIdx.x * NPB;
    for (int i = threadIdx.x; i < NPB * 64; i += 128) {
        float hv = h[node0 * 64 + i];
        h2[i] = pk2(hv, hv);
    }
    __syncthreads();
    int j = threadIdx.x;
    int m = j >> 5;
    int c = (j & 31) * 4;
    const float* W = ((m & 2) ? Wc1 : Wn1) + ((m & 1) ? 64 * 128 : 0);

    ull a0[NPB], a1[NPB];
#pragma unroll
    for (int n = 0; n < NPB; n++) { a0[n] = 0ull; a1[n] = 0ull; }
#pragma unroll 4
    for (int k = 0; k < 64; k++) {
        F4 w; w.f = *(const float4*)&W[k * 128 + c];
#pragma unroll
        for (int n = 0; n < NPB; n++) {
            ull hv = h2[n * 64 + k];
            a0[n] = ffma2(hv, w.u.x, a0[n]);
            a1[n] = ffma2(hv, w.u.y, a1[n]);
        }
    }
#pragma unroll
    for (int n = 0; n < NPB; n++) {
        F4 r; r.u.x = a0[n]; r.u.y = a1[n];
        *(float4*)&g_A[(size_t)(node0 + n) * 512 + m * 128 + c] = r.f;
    }
}

// ---------------------------------------------------------------------------
// K2: initialize output with (h, x)
// ---------------------------------------------------------------------------
__global__ void k_init(const float* __restrict__ h, const float* __restrict__ x,
                       float* __restrict__ out) {
    int nh = N_NODES * NODE_DIM;
    int tot = nh + N_NODES * 3;
    for (int i = blockIdx.x * blockDim.x + threadIdx.x; i < tot; i += gridDim.x * blockDim.x)
        out[i] = (i < nh) ? h[i] : x[i - nh];
}

// ---------------------------------------------------------------------------
// K3: edge kernel. Table-lookup edge path; no k-loops, no spills.
// ---------------------------------------------------------------------------
__global__ void __launch_bounds__(TPB, 2)
k_edge(const float* __restrict__ dist,
       const int*   __restrict__ eidx,
       const float* __restrict__ x,
       const float* __restrict__ bn2,
       const float* __restrict__ Wc2,
       float* __restrict__ out) {
    extern __shared__ float sm[];
    float4* WA_sh = (float4*)sm;               // 1024 f4
    float4* WB_sh = WA_sh + 1024;              // 1024 f4
    float*  gbuf  = (float*)(WB_sh + 1024);    // WPB warps * 1024
    float*  Wc2_sh = gbuf + WPB * 1024;        // 128
    float*  bn2_sh = Wc2_sh + 128;             // 64

    for (int i = threadIdx.x; i < 1024; i += blockDim.x) {
        WA_sh[i] = g_WA[i];
        WB_sh[i] = g_WB[i];
    }
    if (threadIdx.x < 128) Wc2_sh[threadIdx.x] = Wc2[threadIdx.x];
    if (threadIdx.x < 64)  bn2_sh[threadIdx.x] = bn2[threadIdx.x];
    __syncthreads();

    const int lane = threadIdx.x & 31;
    const int wib  = threadIdx.x >> 5;
    const int gw   = blockIdx.x * WPB + wib;
    const int nw   = gridDim.x * WPB;

    F4 wc2_4; wc2_4.f = *(const float4*)&Wc2_sh[4 * lane];
    const float2 bn2_2 = *(const float2*)&bn2_sh[2 * lane];
    float* gb = gbuf + wib * 1024;
    const float4* A4 = (const float4*)g_A;
    const float4* T4 = (const float4*)g_T;     // 64 f4 per table row
    const float4* gb4 = (const float4*)gb;
    float* out_x = out + (size_t)N_NODES * 64;

    for (int base = gw * EPB; base < N_EDGES; base += nw * EPB) {
        int src[EPB], dstn[EPB];
        float cw[EPB];

        // ---- per-edge: table-interp edge path + node terms for both MLPs ----
#pragma unroll
        for (int ee = 0; ee < EPB; ee++) {
            int e = base + ee;
            float d = dist[e];
            int s  = eidx[e];
            int dd = eidx[N_EDGES + e];
            src[ee] = s; dstn[ee] = dd;

            float p = d * (NB / 15.0f);
            int i0 = (int)p;
            i0 = max(0, min(i0, NB - 1));
            float w = p - (float)i0;
            ull w2   = pk2(w, w);
            ull w1m2 = pk2(1.f - w, 1.f - w);
            const float4* t0 = T4 + (size_t)i0 * 64;
            const float4* t1 = t0 + 64;

            // node-MLP hidden: pn = A_ns[src] + A_nd[dst] + lerp(F)
            {
                F4 a;  a.f  = A4[(size_t)s  * 128 + lane];
                F4 b;  b.f  = A4[(size_t)dd * 128 + 32 + lane];
                F4 f0; f0.f = t0[lane];
                F4 f1; f1.f = t1[lane];
                ull px = fadd2(a.u.x, b.u.x);
                ull py = fadd2(a.u.y, b.u.y);
                px = ffma2(w1m2, f0.u.x, px);
                py = ffma2(w1m2, f0.u.y, py);
                px = ffma2(w2, f1.u.x, px);
                py = ffma2(w2, f1.u.y, py);
                float p0, p1, p2, p3;
                upk2(px, p0, p1);
                upk2(py, p2, p3);
                float4 gn = make_float4(silu1(p0), silu1(p1), silu1(p2), silu1(p3));
                *(float4*)&gb[ee * 128 + 4 * lane] = gn;
            }
            // coord-MLP hidden -> scalar cw
            {
                F4 c;  c.f  = A4[(size_t)s  * 128 + 64 + lane];
                F4 dv; dv.f = A4[(size_t)dd * 128 + 96 + lane];
                F4 g0; g0.f = t0[32 + lane];
                F4 g1; g1.f = t1[32 + lane];
                ull px = fadd2(c.u.x, dv.u.x);
                ull py = fadd2(c.u.y, dv.u.y);
                px = ffma2(w1m2, g0.u.x, px);
                py = ffma2(w1m2, g0.u.y, py);
                px = ffma2(w2, g1.u.x, px);
                py = ffma2(w2, g1.u.y, py);
                float p0, p1, p2, p3;
                upk2(px, p0, p1);
                upk2(py, p2, p3);
                float ss = silu1(p0) * wc2_4.f.x + silu1(p1) * wc2_4.f.y
                         + silu1(p2) * wc2_4.f.z + silu1(p3) * wc2_4.f.w;
#pragma unroll
                for (int off = 16; off > 0; off >>= 1)
                    ss += __shfl_xor_sync(0xffffffffu, ss, off);
                cw[ee] = ss;
            }
        }

        // ---- coord scatter (lanes 0..7, one edge each) ----
        if (lane < EPB) {
            float mycw = cw[0]; int ms = src[0], md = dstn[0];
#pragma unroll
            for (int ee = 1; ee < EPB; ee++)
                if (lane == ee) { mycw = cw[ee]; ms = src[ee]; md = dstn[ee]; }
            float dx = x[ms * 3 + 0] - x[md * 3 + 0];
            float dy = x[ms * 3 + 1] - x[md * 3 + 1];
            float dz = x[ms * 3 + 2] - x[md * 3 + 2];
            float len = fmaxf(sqrtf(dx * dx + dy * dy + dz * dz), 1e-8f);
            float inv = mycw / len;
            float* ox = out_x + (size_t)md * 3;
            atomicAdd(&ox[0], dx * inv);
            atomicAdd(&ox[1], dy * inv);
            atomicAdd(&ox[2], dz * inv);
        }
        __syncwarp();

        // ---- phase 2: gn(128) @ Wn2 -> 64 ----
        ull macA[EPB], macB[EPB];
#pragma unroll
        for (int ee = 0; ee < EPB; ee++) {
            macA[ee] = pk2(bn2_2.x, 0.f);
            macB[ee] = pk2(bn2_2.y, 0.f);
        }
#pragma unroll
        for (int i = 0; i < 32; i++) {
            F4 wA; wA.f = WA_sh[i * 32 + lane];
            F4 wB; wB.f = WB_sh[i * 32 + lane];
#pragma unroll
            for (int ee = 0; ee < EPB; ee++) {
                F4 g; g.f = gb4[ee * 32 + i];  // broadcast
                macA[ee] = ffma2(g.u.x, wA.u.x, macA[ee]);
                macA[ee] = ffma2(g.u.y, wA.u.y, macA[ee]);
                macB[ee] = ffma2(g.u.x, wB.u.x, macB[ee]);
                macB[ee] = ffma2(g.u.y, wB.u.y, macB[ee]);
            }
        }

        // ---- node message scatter (scalar atomics: HW REDG fast path) ----
#pragma unroll
        for (int ee = 0; ee < EPB; ee++) {
            float a0, a1, b0, b1;
            upk2(macA[ee], a0, a1);
            upk2(macB[ee], b0, b1);
            float* oh = out + (size_t)dstn[ee] * 64;
            atomicAdd(&oh[2 * lane],     a0 + a1);
            atomicAdd(&oh[2 * lane + 1], b0 + b1);
        }
        __syncwarp();   // gbuf reuse safety across iterations
    }
}

// ---------------------------------------------------------------------------
extern "C" void kernel_launch(void* const* d_in, const int* in_sizes, int n_in,
                              void* d_out, int out_size) {
    const float* h    = (const float*)d_in[0];
    const float* x    = (const float*)d_in[1];
    const float* dist = (const float*)d_in[2];
    const float* We1  = (const float*)d_in[3];
    const float* be1  = (const float*)d_in[4];
    const float* We2  = (const float*)d_in[5];
    const float* be2  = (const float*)d_in[6];
    const float* Wn1  = (const float*)d_in[7];
    const float* bn1  = (const float*)d_in[8];
    const float* Wn2  = (const float*)d_in[9];
    const float* bn2  = (const float*)d_in[10];
    const float* Wc1  = (const float*)d_in[11];
    const float* bc1  = (const float*)d_in[12];
    const float* Wc2  = (const float*)d_in[13];
    const int*   eidx = (const int*)d_in[14];
    float* out = (float*)d_out;

    static bool attr_set = false;
    if (!attr_set) {
        cudaFuncSetAttribute(k_edge, cudaFuncAttributeMaxDynamicSharedMemorySize, 70 * 1024);
        attr_set = true;
    }

    k_fold<<<1, 128>>>(We2, be2, Wn1, bn1, Wc1, bc1, Wn2);
    k_tab<<<NB + 1, 256>>>(We1, be1);
    k_node<<<N_NODES / NPB, 128>>>(h, Wn1, Wc1);
    k_init<<<2048, 256>>>(h, x, out);

    // smem: 8192 (WA,WB) + WPB*1024 (gbuf) + 192 small floats
    const int smem = (8192 + WPB * 1024 + 192) * sizeof(float);  // 66304 B
    k_edge<<<296, TPB, smem>>>(dist, eidx, x, bn2, Wc2, out);
}